// round 2
// baseline (speedup 1.0000x reference)
#include <cuda_runtime.h>
#include <cstdint>

// Problem constants
#define BATCH   8
#define NPTS    16384
#define NPOINT  128
#define NSAMPLE 32
#define C_IN    256
#define C1      259          // 3 + 256
#define C1P     288          // padded to 9*32
#define C_MID   256
#define C_OUT   256
#define R2      0.16f        // f32(0.16): matches jax weak-f64->f32 cast of radius*radius
#define BN_EPS  1e-5f

// ---------------- scratch (device globals; no runtime allocation) ----------------
__device__ int   d_inds[BATCH * NPOINT];                       // FPS indices
__device__ float d_x   [(size_t)BATCH * NPOINT * NSAMPLE * C1P];   // gathered inputs, zero-padded
__device__ float d_h   [(size_t)BATCH * NPOINT * NSAMPLE * C_MID]; // layer1 activations
__device__ float d_w1t [C1P * C_MID];                          // w1 transposed [c][o], zero-padded rows
__device__ float d_w2t [C_MID * C_OUT];                        // w2 transposed [c][o]
__device__ float d_s1[C_MID], d_b1[C_MID], d_s2[C_OUT], d_b2[C_OUT];

// ---------------- prep: transpose weights + fold BN ----------------
__global__ void prep_kernel(const float* __restrict__ w1, const float* __restrict__ w2,
                            const float* __restrict__ g1, const float* __restrict__ be1,
                            const float* __restrict__ m1, const float* __restrict__ v1,
                            const float* __restrict__ g2, const float* __restrict__ be2,
                            const float* __restrict__ m2, const float* __restrict__ v2) {
    int o = threadIdx.x;
    int blk = blockIdx.x;
    if (blk < C1P) {
        int c = blk;
        d_w1t[c * C_MID + o] = (c < C1) ? w1[o * C1 + c] : 0.0f;
        if (blk == 0) {
            float s = g1[o] / sqrtf(v1[o] + BN_EPS);
            d_s1[o] = s;
            d_b1[o] = be1[o] - m1[o] * s;
        } else if (blk == 1) {
            float s = g2[o] / sqrtf(v2[o] + BN_EPS);
            d_s2[o] = s;
            d_b2[o] = be2[o] - m2[o] * s;
        }
    } else {
        int c = blk - C1P;
        d_w2t[c * C_OUT + o] = w2[o * C_MID + c];
    }
}

// ---------------- FPS: one block per batch ----------------
__global__ __launch_bounds__(1024) void fps_kernel(const float* __restrict__ xyz) {
    extern __shared__ float sm[];
    float2* sxy = reinterpret_cast<float2*>(sm);           // 16384 * 8B
    float*  sz  = sm + 2 * NPTS;                           // 16384 * 4B
    __shared__ float rv[32];
    __shared__ int   ri[32];
    __shared__ int   sfar;

    const int b   = blockIdx.x;
    const int tid = threadIdx.x;
    const float* base = xyz + (size_t)b * NPTS * 3;

    for (int i = tid; i < NPTS; i += 1024) {
        float x = base[3 * i], y = base[3 * i + 1], z = base[3 * i + 2];
        sxy[i] = make_float2(x, y);
        sz[i]  = z;
    }
    float dst[16];
#pragma unroll
    for (int p = 0; p < 16; ++p) dst[p] = 1e10f;
    __syncthreads();

    int far = 0;
    for (int j = 0; j < NPOINT; ++j) {
        if (tid == 0) d_inds[b * NPOINT + j] = far;
        float2 cxy = sxy[far];
        float  cz  = sz[far];

        float bv = -1.0f;
        int   bi = 0;
#pragma unroll
        for (int p = 0; p < 16; ++p) {
            int i = tid + (p << 10);
            float2 pxy = sxy[i];
            float  pz  = sz[i];
            // exact: sub, mul, add (no FMA contraction) to match reference fp32 math
            float dx = __fadd_rn(pxy.x, -cxy.x);
            float dy = __fadd_rn(pxy.y, -cxy.y);
            float dz = __fadd_rn(pz,   -cz);
            float d  = __fadd_rn(__fadd_rn(__fmul_rn(dx, dx), __fmul_rn(dy, dy)), __fmul_rn(dz, dz));
            float nd = fminf(dst[p], d);
            dst[p] = nd;
            if (nd > bv) { bv = nd; bi = i; }    // strict > keeps smallest i within thread
        }
        // warp argmax (tie -> smaller index)
#pragma unroll
        for (int off = 16; off > 0; off >>= 1) {
            float ov = __shfl_down_sync(0xffffffffu, bv, off);
            int   oi = __shfl_down_sync(0xffffffffu, bi, off);
            if (ov > bv || (ov == bv && oi < bi)) { bv = ov; bi = oi; }
        }
        if ((tid & 31) == 0) { rv[tid >> 5] = bv; ri[tid >> 5] = bi; }
        __syncthreads();
        if (tid < 32) {
            bv = rv[tid]; bi = ri[tid];
#pragma unroll
            for (int off = 16; off > 0; off >>= 1) {
                float ov = __shfl_down_sync(0xffffffffu, bv, off);
                int   oi = __shfl_down_sync(0xffffffffu, bi, off);
                if (ov > bv || (ov == bv && oi < bi)) { bv = ov; bi = oi; }
            }
            if (tid == 0) sfar = bi;
        }
        __syncthreads();
        far = sfar;
    }
}

// ---------------- ball query + gather: one block per (b, s) ----------------
__global__ __launch_bounds__(256) void bq_gather_kernel(const float* __restrict__ xyz,
                                                        const float* __restrict__ feats) {
    __shared__ int   sidx[NSAMPLE];
    __shared__ float ctr[3];

    const int bs  = blockIdx.x;
    const int b   = bs >> 7;
    const int tid = threadIdx.x;
    const float* xb = xyz + (size_t)b * NPTS * 3;

    if (tid < 32) {
        int ind = d_inds[bs];
        float cx = xb[ind * 3], cy = xb[ind * 3 + 1], cz = xb[ind * 3 + 2];
        if (tid == 0) { ctr[0] = cx; ctr[1] = cy; ctr[2] = cz; }
        int cnt = 0;
        for (int basei = 0; basei < NPTS && cnt < NSAMPLE; basei += 32) {
            int i = basei + tid;
            float dx = __fadd_rn(cx, -xb[i * 3]);
            float dy = __fadd_rn(cy, -xb[i * 3 + 1]);
            float dz = __fadd_rn(cz, -xb[i * 3 + 2]);
            float d2 = __fadd_rn(__fadd_rn(__fmul_rn(dx, dx), __fmul_rn(dy, dy)), __fmul_rn(dz, dz));
            bool pred = d2 < R2;
            unsigned m = __ballot_sync(0xffffffffu, pred);
            int r    = __popc(m & ((1u << tid) - 1u));
            int tot  = __popc(m);
            int take = min(tot, NSAMPLE - cnt);
            if (pred && r < take) sidx[cnt + r] = i;
            cnt += take;
        }
        __syncwarp();
        if (cnt < NSAMPLE) {
            int f = sidx[0];   // always >= 1 hit (centroid itself, d2 = 0)
            for (int pos = cnt + tid; pos < NSAMPLE; pos += 32) sidx[pos] = f;
        }
    }
    __syncthreads();

    const float* fb = feats + (size_t)b * NPTS * C_IN;
    float* xrow = d_x + (size_t)bs * NSAMPLE * C1P;
    for (int k = 0; k < NSAMPLE; ++k) {
        int p = sidx[k];
        float* row = xrow + k * C1P;
        if (tid < 3)  row[tid] = __fadd_rn(xb[p * 3 + tid], -ctr[tid]);
        row[3 + tid] = fb[(size_t)p * C_IN + tid];
        if (tid < C1P - C1) row[C1 + tid] = 0.0f;   // zero pad columns 259..287
    }
}

// ---------------- GEMM helpers (packed f32x2) ----------------
__device__ __forceinline__ unsigned long long pack_dup(float v) {
    unsigned long long r;
    unsigned b = __float_as_uint(v);
    asm("mov.b64 %0, {%1, %1};" : "=l"(r) : "r"(b));
    return r;
}
__device__ __forceinline__ void fma2(unsigned long long& acc, unsigned long long a, unsigned long long b) {
    asm("fma.rn.f32x2 %0, %1, %2, %0;" : "+l"(acc) : "l"(a), "l"(b));
}

// ---------------- GEMM1: h = bn_relu(x @ w1^T), one block per (b,s) ----------------
__global__ __launch_bounds__(256, 2) void gemm1_kernel() {
    __shared__ float sx[32][33];
    __shared__ float sw[32][256];

    const int bs  = blockIdx.x;
    const int tid = threadIdx.x;
    const int oq  = tid & 31;   // lane: o-pair group
    const int kg  = tid >> 5;   // warp: k group (4 rows)

    unsigned long long acc[4][4];
#pragma unroll
    for (int i = 0; i < 4; ++i)
#pragma unroll
        for (int j = 0; j < 4; ++j) acc[i][j] = 0ull;

    const float* xbase = d_x + (size_t)bs * NSAMPLE * C1P;

    for (int ct = 0; ct < C1P / 32; ++ct) {
        int c0 = ct * 32;
        __syncthreads();
        for (int i = tid; i < 32 * 32; i += 256) {
            int k = i >> 5, c = i & 31;
            sx[k][c] = xbase[k * C1P + c0 + c];
        }
        for (int i = tid; i < 32 * 256; i += 256) {
            int c = i >> 8, o = i & 255;
            sw[c][o] = d_w1t[(c0 + c) * C_MID + o];
        }
        __syncthreads();
#pragma unroll
        for (int c = 0; c < 32; ++c) {
            unsigned long long xd[4];
#pragma unroll
            for (int i = 0; i < 4; ++i) xd[i] = pack_dup(sx[kg * 4 + i][c]);
            const unsigned long long* wrow = reinterpret_cast<const unsigned long long*>(&sw[c][0]);
            unsigned long long wd[4];
#pragma unroll
            for (int j = 0; j < 4; ++j) wd[j] = wrow[j * 32 + oq];  // o = j*64 + oq*2 (+0/1)
#pragma unroll
            for (int i = 0; i < 4; ++i)
#pragma unroll
                for (int j = 0; j < 4; ++j) fma2(acc[i][j], xd[i], wd[j]);
        }
    }

    const size_t hbase = (size_t)bs * NSAMPLE * C_MID;
#pragma unroll
    for (int j = 0; j < 4; ++j) {
        int o = j * 64 + oq * 2;
        float s0 = d_s1[o], s1v = d_s1[o + 1];
        float b0 = d_b1[o], b1v = d_b1[o + 1];
#pragma unroll
        for (int i = 0; i < 4; ++i) {
            float lo = __uint_as_float((unsigned)(acc[i][j] & 0xffffffffull));
            float hi = __uint_as_float((unsigned)(acc[i][j] >> 32));
            lo = fmaxf(fmaf(lo, s0, b0), 0.0f);
            hi = fmaxf(fmaf(hi, s1v, b1v), 0.0f);
            *reinterpret_cast<float2*>(&d_h[hbase + (size_t)(kg * 4 + i) * C_MID + o]) = make_float2(lo, hi);
        }
    }
}

// ---------------- GEMM2 + maxpool: out[b][o][s] = max_k bn_relu(h @ w2^T) ----------------
__global__ __launch_bounds__(256, 2) void gemm2_kernel(float* __restrict__ out) {
    __shared__ float sx[32][33];
    __shared__ float sw[32][256];
    __shared__ float red[8][256];

    const int bs  = blockIdx.x;
    const int tid = threadIdx.x;
    const int oq  = tid & 31;
    const int kg  = tid >> 5;

    unsigned long long acc[4][4];
#pragma unroll
    for (int i = 0; i < 4; ++i)
#pragma unroll
        for (int j = 0; j < 4; ++j) acc[i][j] = 0ull;

    const float* xbase = d_h + (size_t)bs * NSAMPLE * C_MID;

    for (int ct = 0; ct < C_MID / 32; ++ct) {
        int c0 = ct * 32;
        __syncthreads();
        for (int i = tid; i < 32 * 32; i += 256) {
            int k = i >> 5, c = i & 31;
            sx[k][c] = xbase[(size_t)k * C_MID + c0 + c];
        }
        for (int i = tid; i < 32 * 256; i += 256) {
            int c = i >> 8, o = i & 255;
            sw[c][o] = d_w2t[(c0 + c) * C_OUT + o];
        }
        __syncthreads();
#pragma unroll
        for (int c = 0; c < 32; ++c) {
            unsigned long long xd[4];
#pragma unroll
            for (int i = 0; i < 4; ++i) xd[i] = pack_dup(sx[kg * 4 + i][c]);
            const unsigned long long* wrow = reinterpret_cast<const unsigned long long*>(&sw[c][0]);
            unsigned long long wd[4];
#pragma unroll
            for (int j = 0; j < 4; ++j) wd[j] = wrow[j * 32 + oq];
#pragma unroll
            for (int i = 0; i < 4; ++i)
#pragma unroll
                for (int j = 0; j < 4; ++j) fma2(acc[i][j], xd[i], wd[j]);
        }
    }

#pragma unroll
    for (int j = 0; j < 4; ++j) {
        int o = j * 64 + oq * 2;
        float s0 = d_s2[o], s1v = d_s2[o + 1];
        float b0 = d_b2[o], b1v = d_b2[o + 1];
        float m0 = 0.0f, m1 = 0.0f;   // relu output >= 0, so 0 is identity for max
#pragma unroll
        for (int i = 0; i < 4; ++i) {
            float lo = __uint_as_float((unsigned)(acc[i][j] & 0xffffffffull));
            float hi = __uint_as_float((unsigned)(acc[i][j] >> 32));
            lo = fmaxf(fmaf(lo, s0, b0), 0.0f);
            hi = fmaxf(fmaf(hi, s1v, b1v), 0.0f);
            m0 = fmaxf(m0, lo);
            m1 = fmaxf(m1, hi);
        }
        red[kg][o]     = m0;
        red[kg][o + 1] = m1;
    }
    __syncthreads();
    float m = red[0][tid];
#pragma unroll
    for (int r = 1; r < 8; ++r) m = fmaxf(m, red[r][tid]);
    int b = bs >> 7, s = bs & 127;
    out[((size_t)b * C_OUT + tid) * NPOINT + s] = m;
}

// ---------------- launch ----------------
extern "C" void kernel_launch(void* const* d_in, const int* in_sizes, int n_in,
                              void* d_out, int out_size) {
    const float* xyz   = (const float*)d_in[0];
    const float* feats = (const float*)d_in[1];
    const float* w1    = (const float*)d_in[2];
    const float* g1    = (const float*)d_in[3];
    const float* be1   = (const float*)d_in[4];
    const float* m1    = (const float*)d_in[5];
    const float* v1    = (const float*)d_in[6];
    const float* w2    = (const float*)d_in[7];
    const float* g2    = (const float*)d_in[8];
    const float* be2   = (const float*)d_in[9];
    const float* m2    = (const float*)d_in[10];
    const float* v2    = (const float*)d_in[11];
    float* out = (float*)d_out;

    cudaFuncSetAttribute(fps_kernel, cudaFuncAttributeMaxDynamicSharedMemorySize, 3 * NPTS * 4);

    prep_kernel<<<C1P + C_MID, 256>>>(w1, w2, g1, be1, m1, v1, g2, be2, m2, v2);
    fps_kernel<<<BATCH, 1024, 3 * NPTS * 4>>>(xyz);
    bq_gather_kernel<<<BATCH * NPOINT, 256>>>(xyz, feats);
    gemm1_kernel<<<BATCH * NPOINT, 256>>>();
    gemm2_kernel<<<BATCH * NPOINT, 256>>>(out);
}

// round 4
// speedup vs baseline: 1.5930x; 1.5930x over previous
#include <cuda_runtime.h>
#include <cuda_bf16.h>
#include <cstdint>

#define BATCH   8
#define NPTS    16384
#define NPOINT  128
#define NSAMPLE 32
#define C_IN    256
#define C1      259
#define K1      288
#define K2      256
#define NTILE   256
#define R2      0.16f
#define BN_EPS  1e-5f

// ---------------- device scratch ----------------
__device__ int d_inds[BATCH * NPOINT];
__device__ __align__(16) __nv_bfloat16 d_xh[(size_t)NTILE * 128 * K1];
__device__ __align__(16) __nv_bfloat16 d_xl[(size_t)NTILE * 128 * K1];
__device__ __align__(16) __nv_bfloat16 d_hh[(size_t)NTILE * 128 * K2];
__device__ __align__(16) __nv_bfloat16 d_hl[(size_t)NTILE * 128 * K2];
__device__ __align__(16) __nv_bfloat16 d_w1h[256 * K1];
__device__ __align__(16) __nv_bfloat16 d_w1l[256 * K1];
__device__ __align__(16) __nv_bfloat16 d_w2h[256 * K2];
__device__ __align__(16) __nv_bfloat16 d_w2l[256 * K2];
__device__ float d_s1[256], d_b1[256], d_s2[256], d_b2[256];

// ---------------- low-level helpers (all sm_80-portable) ----------------
__device__ __forceinline__ uint32_t smem_u32(const void* p) {
    uint32_t a;
    asm("{ .reg .u64 t; cvta.to.shared.u64 t, %1; cvt.u32.u64 %0, t; }" : "=r"(a) : "l"(p));
    return a;
}
__device__ __forceinline__ void cp16(uint32_t dst, const void* src) {
    uint64_t g = __cvta_generic_to_global(src);
    asm volatile("cp.async.cg.shared.global [%0], [%1], 16;" :: "r"(dst), "l"(g) : "memory");
}
__device__ __forceinline__ void cp_commit() {
    asm volatile("cp.async.commit_group;" ::: "memory");
}
template<int N> __device__ __forceinline__ void cp_wait() {
    asm volatile("cp.async.wait_group %0;" :: "n"(N) : "memory");
}
__device__ __forceinline__ void ldsm4(uint32_t& r0, uint32_t& r1, uint32_t& r2, uint32_t& r3, uint32_t addr) {
    asm volatile("ldmatrix.sync.aligned.m8n8.x4.shared.b16 {%0,%1,%2,%3}, [%4];"
                 : "=r"(r0), "=r"(r1), "=r"(r2), "=r"(r3) : "r"(addr));
}
__device__ __forceinline__ void mma16816(float* d, const uint32_t* a, const uint32_t* b) {
    asm volatile(
        "mma.sync.aligned.m16n8k16.row.col.f32.bf16.bf16.f32 "
        "{%0,%1,%2,%3}, {%4,%5,%6,%7}, {%8,%9}, {%0,%1,%2,%3};"
        : "+f"(d[0]), "+f"(d[1]), "+f"(d[2]), "+f"(d[3])
        : "r"(a[0]), "r"(a[1]), "r"(a[2]), "r"(a[3]), "r"(b[0]), "r"(b[1]));
}
__device__ __forceinline__ void split_pack(float v0, float v1, uint32_t& hi, uint32_t& lo) {
    __nv_bfloat16 h0 = __float2bfloat16(v0);
    __nv_bfloat16 h1 = __float2bfloat16(v1);
    __nv_bfloat16 l0 = __float2bfloat16(v0 - __bfloat162float(h0));
    __nv_bfloat16 l1 = __float2bfloat16(v1 - __bfloat162float(h1));
    hi = (uint32_t)__bfloat16_as_ushort(h0) | ((uint32_t)__bfloat16_as_ushort(h1) << 16);
    lo = (uint32_t)__bfloat16_as_ushort(l0) | ((uint32_t)__bfloat16_as_ushort(l1) << 16);
}

// ---------------- prep: BN fold + weight split (plain [o][c] layout) ----------------
__global__ void prep_kernel(const float* __restrict__ w1, const float* __restrict__ w2,
                            const float* __restrict__ g1, const float* __restrict__ be1,
                            const float* __restrict__ m1, const float* __restrict__ v1,
                            const float* __restrict__ g2, const float* __restrict__ be2,
                            const float* __restrict__ m2, const float* __restrict__ v2) {
    if (blockIdx.x == 0) {
        int o = threadIdx.x;
        float s = g1[o] / sqrtf(v1[o] + BN_EPS);
        d_s1[o] = s; d_b1[o] = be1[o] - m1[o] * s;
        float t = g2[o] / sqrtf(v2[o] + BN_EPS);
        d_s2[o] = t; d_b2[o] = be2[o] - m2[o] * t;
    }
    int idx = blockIdx.x * 256 + threadIdx.x;
    const int T1 = 256 * K1;                // 73728
    float v; __nv_bfloat16 *ph, *pl; int e;
    if (idx < T1) {
        int o = idx / K1, c = idx - o * K1;
        v = (c < C1) ? w1[o * C1 + c] : 0.0f;
        ph = d_w1h; pl = d_w1l; e = o * K1 + c;
    } else {
        int k = idx - T1;
        if (k >= 256 * K2) return;
        int o = k >> 8, c = k & 255;
        v = w2[o * 256 + c];
        ph = d_w2h; pl = d_w2l; e = o * K2 + c;
    }
    __nv_bfloat16 hb = __float2bfloat16(v);
    ph[e] = hb;
    pl[e] = __float2bfloat16(v - __bfloat162float(hb));
}

// ---------------- FPS (exact fp32 math) ----------------
__global__ __launch_bounds__(1024) void fps_kernel(const float* __restrict__ xyz) {
    extern __shared__ float sm[];
    float2* sxy = reinterpret_cast<float2*>(sm);
    float*  sz  = sm + 2 * NPTS;
    __shared__ float rv[32];
    __shared__ int   ri[32];
    __shared__ int   sfar;

    const int b   = blockIdx.x;
    const int tid = threadIdx.x;
    const float* base = xyz + (size_t)b * NPTS * 3;

    for (int i = tid; i < NPTS; i += 1024) {
        sxy[i] = make_float2(base[3 * i], base[3 * i + 1]);
        sz[i]  = base[3 * i + 2];
    }
    float dst[16];
#pragma unroll
    for (int p = 0; p < 16; ++p) dst[p] = 1e10f;
    __syncthreads();

    int far = 0;
    for (int j = 0; j < NPOINT; ++j) {
        if (tid == 0) d_inds[b * NPOINT + j] = far;
        float2 cxy = sxy[far];
        float  cz  = sz[far];
        float bv = -1.0f;
        int   bi = 0;
#pragma unroll
        for (int p = 0; p < 16; ++p) {
            int i = tid + (p << 10);
            float2 pxy = sxy[i];
            float dx = __fadd_rn(pxy.x, -cxy.x);
            float dy = __fadd_rn(pxy.y, -cxy.y);
            float dz = __fadd_rn(sz[i], -cz);
            float d  = __fadd_rn(__fadd_rn(__fmul_rn(dx, dx), __fmul_rn(dy, dy)), __fmul_rn(dz, dz));
            float nd = fminf(dst[p], d);
            dst[p] = nd;
            if (nd > bv) { bv = nd; bi = i; }
        }
#pragma unroll
        for (int off = 16; off > 0; off >>= 1) {
            float ov = __shfl_down_sync(0xffffffffu, bv, off);
            int   oi = __shfl_down_sync(0xffffffffu, bi, off);
            if (ov > bv || (ov == bv && oi < bi)) { bv = ov; bi = oi; }
        }
        if ((tid & 31) == 0) { rv[tid >> 5] = bv; ri[tid >> 5] = bi; }
        __syncthreads();
        if (tid < 32) {
            bv = rv[tid]; bi = ri[tid];
#pragma unroll
            for (int off = 16; off > 0; off >>= 1) {
                float ov = __shfl_down_sync(0xffffffffu, bv, off);
                int   oi = __shfl_down_sync(0xffffffffu, bi, off);
                if (ov > bv || (ov == bv && oi < bi)) { bv = ov; bi = oi; }
            }
            if (tid == 0) sfar = bi;
        }
        __syncthreads();
        far = sfar;
    }
}

// ---------------- ball query + gather -> bf16 hi/lo A rows (plain layout) ----------------
__global__ __launch_bounds__(256) void bq_gather_kernel(const float* __restrict__ xyz,
                                                        const float* __restrict__ feats) {
    __shared__ int   sidx[NSAMPLE];
    __shared__ float ctr[3];
    const int g   = blockIdx.x;          // centroid 0..1023
    const int b   = g >> 7;
    const int tid = threadIdx.x;
    const float* xb = xyz + (size_t)b * NPTS * 3;

    if (tid < 32) {
        int ind = d_inds[g];
        float cx = xb[ind * 3], cy = xb[ind * 3 + 1], cz = xb[ind * 3 + 2];
        if (tid == 0) { ctr[0] = cx; ctr[1] = cy; ctr[2] = cz; }
        int cnt = 0;
        for (int basei = 0; basei < NPTS && cnt < NSAMPLE; basei += 32) {
            int i = basei + tid;
            float dx = __fadd_rn(cx, -xb[i * 3]);
            float dy = __fadd_rn(cy, -xb[i * 3 + 1]);
            float dz = __fadd_rn(cz, -xb[i * 3 + 2]);
            float d2 = __fadd_rn(__fadd_rn(__fmul_rn(dx, dx), __fmul_rn(dy, dy)), __fmul_rn(dz, dz));
            bool pred = d2 < R2;
            unsigned m = __ballot_sync(0xffffffffu, pred);
            int r    = __popc(m & ((1u << tid) - 1u));
            int take = min(__popc(m), NSAMPLE - cnt);
            if (pred && r < take) sidx[cnt + r] = i;
            cnt += take;
        }
        __syncwarp();
        if (cnt < NSAMPLE) {
            int f = sidx[0];
            for (int pos = cnt + tid; pos < NSAMPLE; pos += 32) sidx[pos] = f;
        }
    }
    __syncthreads();

    const float* fb = feats + (size_t)b * NPTS * C_IN;
    const size_t tbase = ((size_t)(g >> 2) * 128 + (size_t)(g & 3) * 32) * K1;
    for (int idx = tid; idx < 32 * (K1 / 2); idx += 256) {
        int k = idx / (K1 / 2), q = idx - k * (K1 / 2);
        int c0 = 2 * q, c1 = c0 + 1;
        int p = sidx[k];
        float v0 = (c0 < 3) ? __fadd_rn(xb[p * 3 + c0], -ctr[c0])
                 : (c0 < C1 ? fb[(size_t)p * C_IN + (c0 - 3)] : 0.0f);
        float v1 = (c1 < 3) ? __fadd_rn(xb[p * 3 + c1], -ctr[c1])
                 : (c1 < C1 ? fb[(size_t)p * C_IN + (c1 - 3)] : 0.0f);
        uint32_t hi, lo;
        split_pack(v0, v1, hi, lo);
        size_t e = tbase + (size_t)k * K1 + c0;
        *(uint32_t*)((char*)d_xh + e * 2) = hi;
        *(uint32_t*)((char*)d_xl + e * 2) = lo;
    }
}

// ---------------- mma GEMM: C[128x256] = A(hi,lo)[128xK] @ W(hi,lo)[256xK]^T ----------------
// SECOND=false: A from d_xh/d_xl, W=w1, epilogue BN1+ReLU -> d_hh/d_hl
// SECOND=true : A from d_hh/d_hl, W=w2, epilogue BN2+ReLU+maxpool(32) -> out
template<int K, int SAB, bool SECOND>
__global__ __launch_bounds__(512, 1) void gemm_kernel(float* __restrict__ out) {
    extern __shared__ __align__(128) char smem[];
    constexpr int NK   = K / 16;
    constexpr int A_SZ = 128 * SAB;
    constexpr int B_OFF = 2 * A_SZ;

    const uint32_t sb = smem_u32(smem);
    const int tid  = threadIdx.x;
    const int lane = tid & 31, wid = tid >> 5;
    const int mh = wid >> 3, nb = wid & 7;

    const __nv_bfloat16* Ah_src = SECOND ? d_hh : d_xh;
    const __nv_bfloat16* Al_src = SECOND ? d_hl : d_xl;
    const __nv_bfloat16* Wh = SECOND ? d_w2h : d_w1h;
    const __nv_bfloat16* Wl = SECOND ? d_w2l : d_w1l;

    // ---- prologue: A tile (resident) + first two W chunks ----
    {
        constexpr int asegs = K / 8;
        constexpr int atot  = 128 * asegs * 2;
        const size_t gbase = (size_t)blockIdx.x * 128 * K;
#pragma unroll
        for (int i = tid; i < atot; i += 512) {
            int mat = i / (128 * asegs);
            int rem = i - mat * (128 * asegs);
            int r = rem / asegs, s = rem - r * asegs;
            const __nv_bfloat16* src = (mat ? Al_src : Ah_src) + gbase + (size_t)r * K + s * 8;
            cp16(sb + mat * A_SZ + r * SAB + s * 16, src);
        }
        for (int i = tid; i < 1024; i += 512) {
            int mat = i >> 9, rem = i & 511, o = rem >> 1, s = rem & 1;
            cp16(sb + B_OFF + mat * 12288 + o * 48 + s * 16,
                 (mat ? Wl : Wh) + o * K + s * 8);
        }
        cp_commit();
        for (int i = tid; i < 1024; i += 512) {
            int mat = i >> 9, rem = i & 511, o = rem >> 1, s = rem & 1;
            cp16(sb + B_OFF + 24576 + mat * 12288 + o * 48 + s * 16,
                 (mat ? Wl : Wh) + o * K + 16 + s * 8);
        }
        cp_commit();
    }

    float acc[4][4][4];
#pragma unroll
    for (int a = 0; a < 4; ++a)
#pragma unroll
        for (int b = 0; b < 4; ++b)
#pragma unroll
            for (int c = 0; c < 4; ++c) acc[a][b][c] = 0.0f;

    const int lr   = lane & 15;
    const int ahi  = (lane >> 4) * 16;               // byte offset for k+8 half
    const int brow = (lane & 7) | ((lane >> 4) << 3);
    const int bko  = ((lane >> 3) & 1) * 16;

    // ---- main k loop ----
    for (int ks = 0; ks < NK; ++ks) {
        if (ks + 2 < NK) cp_wait<1>(); else cp_wait<0>();
        __syncthreads();
        const int buf = ks & 1;
        const uint32_t bbase = sb + B_OFF + buf * 24576 + (nb * 32 + brow) * 48 + bko;

        uint32_t bh[4][2], bl[4][2];
#pragma unroll
        for (int ntp = 0; ntp < 2; ++ntp) {
            uint32_t r0, r1, r2, r3;
            ldsm4(r0, r1, r2, r3, bbase + ntp * 16 * 48);
            bh[ntp * 2][0] = r0; bh[ntp * 2][1] = r1;
            bh[ntp * 2 + 1][0] = r2; bh[ntp * 2 + 1][1] = r3;
            ldsm4(r0, r1, r2, r3, bbase + ntp * 16 * 48 + 12288);
            bl[ntp * 2][0] = r0; bl[ntp * 2][1] = r1;
            bl[ntp * 2 + 1][0] = r2; bl[ntp * 2 + 1][1] = r3;
        }

        const int kb = ks * 32;   // byte offset of chunk k0 in A rows
#pragma unroll
        for (int mt = 0; mt < 4; ++mt) {
            const uint32_t arow = sb + (mh * 64 + mt * 16 + lr) * SAB + kb + ahi;
            uint32_t ah[4], al[4];
            ldsm4(ah[0], ah[1], ah[2], ah[3], arow);
            ldsm4(al[0], al[1], al[2], al[3], arow + A_SZ);
#pragma unroll
            for (int nt = 0; nt < 4; ++nt) {
                mma16816(acc[mt][nt], ah, bh[nt]);
                mma16816(acc[mt][nt], al, bh[nt]);
                mma16816(acc[mt][nt], ah, bl[nt]);
            }
        }
        __syncthreads();
        const int nx = ks + 2;
        if (nx < NK) {
            for (int i = tid; i < 1024; i += 512) {
                int mat = i >> 9, rem = i & 511, o = rem >> 1, s = rem & 1;
                cp16(sb + B_OFF + buf * 24576 + mat * 12288 + o * 48 + s * 16,
                     (mat ? Wl : Wh) + o * K + nx * 16 + s * 8);
            }
            cp_commit();
        }
    }

    // ---- epilogue ----
    if (!SECOND) {
        const size_t hb = (size_t)blockIdx.x * 128 * 256;
#pragma unroll
        for (int mt = 0; mt < 4; ++mt) {
            int row0 = mh * 64 + mt * 16 + (lane >> 2);
#pragma unroll
            for (int nt = 0; nt < 4; ++nt) {
                int col = nb * 32 + nt * 8 + 2 * (lane & 3);
                float s0 = d_s1[col], s1v = d_s1[col + 1];
                float b0 = d_b1[col], b1v = d_b1[col + 1];
                float f00 = fmaxf(fmaf(acc[mt][nt][0], s0, b0), 0.0f);
                float f01 = fmaxf(fmaf(acc[mt][nt][1], s1v, b1v), 0.0f);
                float f10 = fmaxf(fmaf(acc[mt][nt][2], s0, b0), 0.0f);
                float f11 = fmaxf(fmaf(acc[mt][nt][3], s1v, b1v), 0.0f);
                uint32_t h0, l0, h1, l1;
                split_pack(f00, f01, h0, l0);
                split_pack(f10, f11, h1, l1);
                size_t e0 = hb + (size_t)row0 * 256 + col;
                size_t e1 = e0 + 8 * 256;
                *(uint32_t*)((char*)d_hh + e0 * 2) = h0;
                *(uint32_t*)((char*)d_hl + e0 * 2) = l0;
                *(uint32_t*)((char*)d_hh + e1 * 2) = h1;
                *(uint32_t*)((char*)d_hl + e1 * 2) = l1;
            }
        }
    } else {
#pragma unroll
        for (int p = 0; p < 2; ++p) {
#pragma unroll
            for (int nt = 0; nt < 4; ++nt) {
                int col = nb * 32 + nt * 8 + 2 * (lane & 3);
                float s0 = d_s2[col], s1v = d_s2[col + 1];
                float b0 = d_b2[col], b1v = d_b2[col + 1];
                float v0 = 0.0f, v1 = 0.0f;
#pragma unroll
                for (int m = 0; m < 2; ++m) {
                    int mt = 2 * p + m;
                    v0 = fmaxf(v0, fmaxf(fmaf(acc[mt][nt][0], s0, b0),
                                         fmaf(acc[mt][nt][2], s0, b0)));
                    v1 = fmaxf(v1, fmaxf(fmaf(acc[mt][nt][1], s1v, b1v),
                                         fmaf(acc[mt][nt][3], s1v, b1v)));
                }
#pragma unroll
                for (int o = 4; o < 32; o <<= 1) {
                    v0 = fmaxf(v0, __shfl_xor_sync(0xffffffffu, v0, o));
                    v1 = fmaxf(v1, __shfl_xor_sync(0xffffffffu, v1, o));
                }
                if ((lane >> 2) == 0) {
                    int g = blockIdx.x * 4 + mh * 2 + p;
                    int bb = g >> 7, si = g & 127;
                    out[((size_t)bb * 256 + col) * 128 + si]     = v0;
                    out[((size_t)bb * 256 + col + 1) * 128 + si] = v1;
                }
            }
        }
    }
}

// ---------------- launch ----------------
extern "C" void kernel_launch(void* const* d_in, const int* in_sizes, int n_in,
                              void* d_out, int out_size) {
    const float* xyz   = (const float*)d_in[0];
    const float* feats = (const float*)d_in[1];
    const float* w1    = (const float*)d_in[2];
    const float* g1    = (const float*)d_in[3];
    const float* be1   = (const float*)d_in[4];
    const float* m1    = (const float*)d_in[5];
    const float* v1    = (const float*)d_in[6];
    const float* w2    = (const float*)d_in[7];
    const float* g2    = (const float*)d_in[8];
    const float* be2   = (const float*)d_in[9];
    const float* m2    = (const float*)d_in[10];
    const float* v2    = (const float*)d_in[11];
    float* out = (float*)d_out;

    constexpr int SMEM1 = 2 * 128 * 592 + 49152;   // 200704
    constexpr int SMEM2 = 2 * 128 * 528 + 49152;   // 184320

    cudaFuncSetAttribute(fps_kernel, cudaFuncAttributeMaxDynamicSharedMemorySize, 3 * NPTS * 4);
    cudaFuncSetAttribute(gemm_kernel<K1, 592, false>, cudaFuncAttributeMaxDynamicSharedMemorySize, SMEM1);
    cudaFuncSetAttribute(gemm_kernel<K2, 528, true>,  cudaFuncAttributeMaxDynamicSharedMemorySize, SMEM2);

    prep_kernel<<<544, 256>>>(w1, w2, g1, be1, m1, v1, g2, be2, m2, v2);
    fps_kernel<<<BATCH, 1024, 3 * NPTS * 4>>>(xyz);
    bq_gather_kernel<<<BATCH * NPOINT, 256>>>(xyz, feats);
    gemm_kernel<K1, 592, false><<<NTILE, 512, SMEM1>>>(out);
    gemm_kernel<K2, 528, true><<<NTILE, 512, SMEM2>>>(out);
}

// round 5
// speedup vs baseline: 1.9970x; 1.2536x over previous
#include <cuda_runtime.h>
#include <cuda_bf16.h>
#include <cstdint>

#define BATCH   8
#define NPTS    16384
#define NPOINT  128
#define NSAMPLE 32
#define C_IN    256
#define C1      259
#define K1      288
#define K2      256
#define NTILE   256
#define R2      0.16f
#define BN_EPS  1e-5f

// fused gemm smem layout
#define SAB    592                      // bytes per A row (576 data + 16 pad)
#define A_SZ   (128 * SAB)              // 75776 (one of hi/lo)
#define W_OFF  (2 * A_SZ)               // 151552
#define WCH    24576                    // one weight chunk (hi 12288 + lo 12288)
#define GSMEM  (W_OFF + 3 * WCH)        // 225280
#define NCH    (K1 / 16 + K2 / 16)      // 34 chunks total

// ---------------- device scratch ----------------
__device__ int d_inds[BATCH * NPOINT];
__device__ __align__(16) __nv_bfloat16 d_xh[(size_t)NTILE * 128 * K1];
__device__ __align__(16) __nv_bfloat16 d_xl[(size_t)NTILE * 128 * K1];
__device__ __align__(16) __nv_bfloat16 d_w1h[256 * K1];
__device__ __align__(16) __nv_bfloat16 d_w1l[256 * K1];
__device__ __align__(16) __nv_bfloat16 d_w2h[256 * K2];
__device__ __align__(16) __nv_bfloat16 d_w2l[256 * K2];
__device__ float d_s1[256], d_b1[256], d_s2[256], d_b2[256];

// ---------------- low-level helpers (sm_90-base portable) ----------------
__device__ __forceinline__ uint32_t smem_u32(const void* p) {
    uint32_t a;
    asm("{ .reg .u64 t; cvta.to.shared.u64 t, %1; cvt.u32.u64 %0, t; }" : "=r"(a) : "l"(p));
    return a;
}
__device__ __forceinline__ void cp16(uint32_t dst, const void* src) {
    uint64_t g = __cvta_generic_to_global(src);
    asm volatile("cp.async.cg.shared.global [%0], [%1], 16;" :: "r"(dst), "l"(g) : "memory");
}
__device__ __forceinline__ void cp_commit() {
    asm volatile("cp.async.commit_group;" ::: "memory");
}
template<int N> __device__ __forceinline__ void cp_wait() {
    asm volatile("cp.async.wait_group %0;" :: "n"(N) : "memory");
}
__device__ __forceinline__ void ldsm4(uint32_t& r0, uint32_t& r1, uint32_t& r2, uint32_t& r3, uint32_t addr) {
    asm volatile("ldmatrix.sync.aligned.m8n8.x4.shared.b16 {%0,%1,%2,%3}, [%4];"
                 : "=r"(r0), "=r"(r1), "=r"(r2), "=r"(r3) : "r"(addr));
}
__device__ __forceinline__ void mma16816(float* d, const uint32_t* a, const uint32_t* b) {
    asm volatile(
        "mma.sync.aligned.m16n8k16.row.col.f32.bf16.bf16.f32 "
        "{%0,%1,%2,%3}, {%4,%5,%6,%7}, {%8,%9}, {%0,%1,%2,%3};"
        : "+f"(d[0]), "+f"(d[1]), "+f"(d[2]), "+f"(d[3])
        : "r"(a[0]), "r"(a[1]), "r"(a[2]), "r"(a[3]), "r"(b[0]), "r"(b[1]));
}
__device__ __forceinline__ void split_pack(float v0, float v1, uint32_t& hi, uint32_t& lo) {
    __nv_bfloat16 h0 = __float2bfloat16(v0);
    __nv_bfloat16 h1 = __float2bfloat16(v1);
    __nv_bfloat16 l0 = __float2bfloat16(v0 - __bfloat162float(h0));
    __nv_bfloat16 l1 = __float2bfloat16(v1 - __bfloat162float(h1));
    hi = (uint32_t)__bfloat16_as_ushort(h0) | ((uint32_t)__bfloat16_as_ushort(h1) << 16);
    lo = (uint32_t)__bfloat16_as_ushort(l0) | ((uint32_t)__bfloat16_as_ushort(l1) << 16);
}
__device__ __forceinline__ void st_cluster_u64(uint32_t saddr, uint32_t rank, unsigned long long v) {
    asm volatile("{\n\t.reg .b32 r;\n\tmapa.shared::cluster.u32 r, %0, %1;\n\t"
                 "st.shared::cluster.u64 [r], %2;\n\t}"
                 :: "r"(saddr), "r"(rank), "l"(v) : "memory");
}
__device__ __forceinline__ void st_cluster_f32(uint32_t saddr, uint32_t rank, float v) {
    asm volatile("{\n\t.reg .b32 r;\n\tmapa.shared::cluster.u32 r, %0, %1;\n\t"
                 "st.shared::cluster.f32 [r], %2;\n\t}"
                 :: "r"(saddr), "r"(rank), "f"(v) : "memory");
}
__device__ __forceinline__ void cluster_sync_() {
    asm volatile("barrier.cluster.arrive.aligned;" ::: "memory");
    asm volatile("barrier.cluster.wait.aligned;" ::: "memory");
}

// ---------------- prep: BN fold + weight split ----------------
__global__ void prep_kernel(const float* __restrict__ w1, const float* __restrict__ w2,
                            const float* __restrict__ g1, const float* __restrict__ be1,
                            const float* __restrict__ m1, const float* __restrict__ v1,
                            const float* __restrict__ g2, const float* __restrict__ be2,
                            const float* __restrict__ m2, const float* __restrict__ v2) {
    if (blockIdx.x == 0) {
        int o = threadIdx.x;
        float s = g1[o] / sqrtf(v1[o] + BN_EPS);
        d_s1[o] = s; d_b1[o] = be1[o] - m1[o] * s;
        float t = g2[o] / sqrtf(v2[o] + BN_EPS);
        d_s2[o] = t; d_b2[o] = be2[o] - m2[o] * t;
    }
    int idx = blockIdx.x * 256 + threadIdx.x;
    const int T1 = 256 * K1;
    float v; __nv_bfloat16 *ph, *pl; int e;
    if (idx < T1) {
        int o = idx / K1, c = idx - o * K1;
        v = (c < C1) ? w1[o * C1 + c] : 0.0f;
        ph = d_w1h; pl = d_w1l; e = o * K1 + c;
    } else {
        int k = idx - T1;
        if (k >= 256 * K2) return;
        int o = k >> 8, c = k & 255;
        v = w2[o * 256 + c];
        ph = d_w2h; pl = d_w2l; e = o * K2 + c;
    }
    __nv_bfloat16 hb = __float2bfloat16(v);
    ph[e] = hb;
    pl[e] = __float2bfloat16(v - __bfloat162float(hb));
}

// ---------------- FPS: cluster of 8 CTAs per batch, points in registers ----------------
__global__ __cluster_dims__(8, 1, 1) __launch_bounds__(1024, 1)
void fps_kernel(const float* __restrict__ xyz) {
    __shared__ uint32_t redv[32];
    __shared__ int      redi[32];
    __shared__ float    redx[32], redy[32], redz[32];
    __shared__ unsigned long long mb_key[2][8];
    __shared__ float    mb_x[2][8], mb_y[2][8], mb_z[2][8];

    const int b    = blockIdx.x >> 3;
    const int rank = blockIdx.x & 7;
    const int tid  = threadIdx.x;
    const int lane = tid & 31, w = tid >> 5;
    const float* base = xyz + (size_t)b * NPTS * 3;
    const int i0 = rank * 2048 + tid * 2;

    float x0 = base[i0 * 3],     y0 = base[i0 * 3 + 1], z0 = base[i0 * 3 + 2];
    float x1 = base[i0 * 3 + 3], y1 = base[i0 * 3 + 4], z1 = base[i0 * 3 + 5];
    float d0 = 1e10f, d1 = 1e10f;
    float cx = base[0], cy = base[1], cz = base[2];
    int far = 0;

    const uint32_t mbk = smem_u32(&mb_key[0][0]);
    const uint32_t mbx = smem_u32(&mb_x[0][0]);
    const uint32_t mby = smem_u32(&mb_y[0][0]);
    const uint32_t mbz = smem_u32(&mb_z[0][0]);

    cluster_sync_();

    for (int j = 0; j < NPOINT; ++j) {
        if (rank == 0 && tid == 0) d_inds[b * NPOINT + j] = far;
        const int p = j & 1;

        // exact fp32: sub, mul, add-add (matches reference ordering)
        float ax = __fadd_rn(x0, -cx), ay = __fadd_rn(y0, -cy), az = __fadd_rn(z0, -cz);
        float t0 = __fadd_rn(__fadd_rn(__fmul_rn(ax, ax), __fmul_rn(ay, ay)), __fmul_rn(az, az));
        d0 = fminf(d0, t0);
        float bx = __fadd_rn(x1, -cx), by = __fadd_rn(y1, -cy), bz = __fadd_rn(z1, -cz);
        float t1 = __fadd_rn(__fadd_rn(__fmul_rn(bx, bx), __fmul_rn(by, by)), __fmul_rn(bz, bz));
        d1 = fminf(d1, t1);

        // thread best (tie -> smaller index i0)
        float bv; int bi; float wx, wy, wz;
        if (d0 >= d1) { bv = d0; bi = i0;     wx = x0; wy = y0; wz = z0; }
        else          { bv = d1; bi = i0 + 1; wx = x1; wy = y1; wz = z1; }

        // warp argmax: lanes ordered by index, so lowest matching lane = smallest index
        uint32_t vb   = __float_as_uint(bv);       // all dists >= 0 -> bits monotonic
        uint32_t vmax = __reduce_max_sync(0xffffffffu, vb);
        uint32_t msk  = __ballot_sync(0xffffffffu, vb == vmax);
        int src = __ffs(msk) - 1;
        if (lane == 0)   redv[w] = vmax;
        if (lane == src) { redi[w] = bi; redx[w] = wx; redy[w] = wy; redz[w] = wz; }
        __syncthreads();

        if (w == 0) {
            uint32_t v2  = redv[lane];
            uint32_t m2  = __reduce_max_sync(0xffffffffu, v2);
            uint32_t mk2 = __ballot_sync(0xffffffffu, v2 == m2);
            int wl = __ffs(mk2) - 1;
            if (lane == 0) {
                int bi2 = redi[wl];
                unsigned long long key =
                    ((unsigned long long)m2 << 32) | (unsigned long long)(0xFFFFFFFFu - (uint32_t)bi2);
                float fx = redx[wl], fy = redy[wl], fz = redz[wl];
                uint32_t so = (uint32_t)(p * 8 + rank);
#pragma unroll
                for (uint32_t t = 0; t < 8; ++t) {
                    st_cluster_u64(mbk + so * 8, t, key);
                    st_cluster_f32(mbx + so * 4, t, fx);
                    st_cluster_f32(mby + so * 4, t, fy);
                    st_cluster_f32(mbz + so * 4, t, fz);
                }
            }
        }
        cluster_sync_();

        unsigned long long bk = mb_key[p][0];
        int bs = 0;
#pragma unroll
        for (int s = 1; s < 8; ++s) {
            unsigned long long k = mb_key[p][s];
            if (k > bk) { bk = k; bs = s; }
        }
        far = (int)(0xFFFFFFFFu - (uint32_t)bk);
        cx = mb_x[p][bs]; cy = mb_y[p][bs]; cz = mb_z[p][bs];
    }
}

// ---------------- ball query + gather -> bf16 hi/lo A rows ----------------
__global__ __launch_bounds__(256) void bq_gather_kernel(const float* __restrict__ xyz,
                                                        const float* __restrict__ feats) {
    __shared__ int   sidx[NSAMPLE];
    __shared__ float ctr[3];
    const int g   = blockIdx.x;
    const int b   = g >> 7;
    const int tid = threadIdx.x;
    const float* xb = xyz + (size_t)b * NPTS * 3;

    if (tid < 32) {
        int ind = d_inds[g];
        float cx = xb[ind * 3], cy = xb[ind * 3 + 1], cz = xb[ind * 3 + 2];
        if (tid == 0) { ctr[0] = cx; ctr[1] = cy; ctr[2] = cz; }
        int cnt = 0;
        for (int basei = 0; basei < NPTS && cnt < NSAMPLE; basei += 32) {
            int i = basei + tid;
            float dx = __fadd_rn(cx, -xb[i * 3]);
            float dy = __fadd_rn(cy, -xb[i * 3 + 1]);
            float dz = __fadd_rn(cz, -xb[i * 3 + 2]);
            float d2 = __fadd_rn(__fadd_rn(__fmul_rn(dx, dx), __fmul_rn(dy, dy)), __fmul_rn(dz, dz));
            bool pred = d2 < R2;
            unsigned m = __ballot_sync(0xffffffffu, pred);
            int r    = __popc(m & ((1u << tid) - 1u));
            int take = min(__popc(m), NSAMPLE - cnt);
            if (pred && r < take) sidx[cnt + r] = i;
            cnt += take;
        }
        __syncwarp();
        if (cnt < NSAMPLE) {
            int f = sidx[0];
            for (int pos = cnt + tid; pos < NSAMPLE; pos += 32) sidx[pos] = f;
        }
    }
    __syncthreads();

    const float* fb = feats + (size_t)b * NPTS * C_IN;
    const size_t tbase = ((size_t)(g >> 2) * 128 + (size_t)(g & 3) * 32) * K1;
    for (int idx = tid; idx < 32 * (K1 / 2); idx += 256) {
        int k = idx / (K1 / 2), q = idx - k * (K1 / 2);
        int c0 = 2 * q, c1 = c0 + 1;
        int p = sidx[k];
        float v0 = (c0 < 3) ? __fadd_rn(xb[p * 3 + c0], -ctr[c0])
                 : (c0 < C1 ? fb[(size_t)p * C_IN + (c0 - 3)] : 0.0f);
        float v1 = (c1 < 3) ? __fadd_rn(xb[p * 3 + c1], -ctr[c1])
                 : (c1 < C1 ? fb[(size_t)p * C_IN + (c1 - 3)] : 0.0f);
        uint32_t hi, lo;
        split_pack(v0, v1, hi, lo);
        size_t e = tbase + (size_t)k * K1 + c0;
        *(uint32_t*)((char*)d_xh + e * 2) = hi;
        *(uint32_t*)((char*)d_xl + e * 2) = lo;
    }
}

// ---------------- fused GEMM1 + GEMM2 + maxpool (3-stage pipeline, 1 sync/kstep) ----------------
__global__ __launch_bounds__(512, 1) void fused_gemm_kernel(float* __restrict__ out) {
    extern __shared__ __align__(128) char smem[];
    const uint32_t sb = smem_u32(smem);
    const int tid  = threadIdx.x;
    const int lane = tid & 31, wid = tid >> 5;
    const int mh = wid >> 3, nb = wid & 7;

    // weight chunk loader: chunks 0..17 = W1, 18..33 = W2; buffer = ci % 3
    auto load_chunk = [&](int ci) {
        const __nv_bfloat16 *sh, *sl; int koff, kstr;
        if (ci < 18) { sh = d_w1h; sl = d_w1l; koff = ci * 16;        kstr = K1; }
        else         { sh = d_w2h; sl = d_w2l; koff = (ci - 18) * 16; kstr = K2; }
        uint32_t dstb = sb + W_OFF + (ci % 3) * WCH;
        for (int i = tid; i < 1024; i += 512) {
            int mat = i >> 9, rem = i & 511, o = rem >> 1, s2 = rem & 1;
            cp16(dstb + mat * 12288 + o * 48 + s2 * 16,
                 (mat ? sl : sh) + o * kstr + koff + s2 * 8);
        }
    };

    // prologue: A tile (hi+lo) + chunk 0 in group 0; chunks 1, 2 in groups 1, 2
    {
        const size_t gbase = (size_t)blockIdx.x * 128 * K1;
        constexpr int asegs = K1 / 8;          // 36
#pragma unroll
        for (int i = tid; i < 128 * asegs * 2; i += 512) {
            int mat = i / (128 * asegs);
            int rem = i - mat * (128 * asegs);
            int r = rem / asegs, s = rem - r * asegs;
            cp16(sb + mat * A_SZ + r * SAB + s * 16,
                 (mat ? d_xl : d_xh) + gbase + (size_t)r * K1 + s * 8);
        }
        load_chunk(0); cp_commit();
        load_chunk(1); cp_commit();
        load_chunk(2); cp_commit();
    }

    float acc[4][4][4];
#pragma unroll
    for (int a = 0; a < 4; ++a)
#pragma unroll
        for (int b2 = 0; b2 < 4; ++b2)
#pragma unroll
            for (int c = 0; c < 4; ++c) acc[a][b2][c] = 0.0f;

    const int lr   = lane & 15;
    const int ahi  = (lane >> 4) * 16;
    const int brow = (lane & 7) | ((lane >> 4) << 3);
    const int bko  = ((lane >> 3) & 1) * 16;

    for (int g = 0; g < NCH; ++g) {
        if (g == 18) {
            // ---- epilogue 1: BN1+ReLU, re-split -> overwrite A region with h ----
#pragma unroll
            for (int mt = 0; mt < 4; ++mt) {
                int row0 = mh * 64 + mt * 16 + (lane >> 2);
#pragma unroll
                for (int nt = 0; nt < 4; ++nt) {
                    int col = nb * 32 + nt * 8 + 2 * (lane & 3);
                    float s0 = d_s1[col], s1v = d_s1[col + 1];
                    float b0 = d_b1[col], b1v = d_b1[col + 1];
                    float f00 = fmaxf(fmaf(acc[mt][nt][0], s0, b0), 0.0f);
                    float f01 = fmaxf(fmaf(acc[mt][nt][1], s1v, b1v), 0.0f);
                    float f10 = fmaxf(fmaf(acc[mt][nt][2], s0, b0), 0.0f);
                    float f11 = fmaxf(fmaf(acc[mt][nt][3], s1v, b1v), 0.0f);
                    uint32_t h0, l0, h1, l1;
                    split_pack(f00, f01, h0, l0);
                    split_pack(f10, f11, h1, l1);
                    uint32_t o0 = (uint32_t)row0 * SAB + (uint32_t)col * 2;
                    uint32_t o1 = o0 + 8 * SAB;
                    *(uint32_t*)(smem + o0) = h0;
                    *(uint32_t*)(smem + A_SZ + o0) = l0;
                    *(uint32_t*)(smem + o1) = h1;
                    *(uint32_t*)(smem + A_SZ + o1) = l1;
                    acc[mt][nt][0] = 0.0f; acc[mt][nt][1] = 0.0f;
                    acc[mt][nt][2] = 0.0f; acc[mt][nt][3] = 0.0f;
                }
            }
        }

        cp_wait<2>();
        __syncthreads();   // chunk g ready; also guards A rewrite (g==18) and buffer reuse

        const int buf = g % 3;
        const uint32_t bbase = sb + W_OFF + buf * WCH + (nb * 32 + brow) * 48 + bko;
        uint32_t bh[4][2], bl[4][2];
#pragma unroll
        for (int ntp = 0; ntp < 2; ++ntp) {
            uint32_t r0, r1, r2, r3;
            ldsm4(r0, r1, r2, r3, bbase + ntp * 16 * 48);
            bh[ntp * 2][0] = r0; bh[ntp * 2][1] = r1;
            bh[ntp * 2 + 1][0] = r2; bh[ntp * 2 + 1][1] = r3;
            ldsm4(r0, r1, r2, r3, bbase + ntp * 16 * 48 + 12288);
            bl[ntp * 2][0] = r0; bl[ntp * 2][1] = r1;
            bl[ntp * 2 + 1][0] = r2; bl[ntp * 2 + 1][1] = r3;
        }

        const int kb = (g < 18 ? g : g - 18) * 32;
#pragma unroll
        for (int mt = 0; mt < 4; ++mt) {
            const uint32_t arow = sb + (mh * 64 + mt * 16 + lr) * SAB + kb + ahi;
            uint32_t ah[4], al[4];
            ldsm4(ah[0], ah[1], ah[2], ah[3], arow);
            ldsm4(al[0], al[1], al[2], al[3], arow + A_SZ);
#pragma unroll
            for (int nt = 0; nt < 4; ++nt) {
                mma16816(acc[mt][nt], ah, bh[nt]);
                mma16816(acc[mt][nt], al, bh[nt]);
                mma16816(acc[mt][nt], ah, bl[nt]);
            }
        }
        __syncthreads();   // all warps done with buffer (g%3) -> safe to refill

        if (g + 3 < NCH) load_chunk(g + 3);
        cp_commit();
    }

    // ---- epilogue 2: BN2+ReLU + maxpool(32) -> out[b][o][s] ----
#pragma unroll
    for (int p = 0; p < 2; ++p) {
#pragma unroll
        for (int nt = 0; nt < 4; ++nt) {
            int col = nb * 32 + nt * 8 + 2 * (lane & 3);
            float s0 = d_s2[col], s1v = d_s2[col + 1];
            float b0 = d_b2[col], b1v = d_b2[col + 1];
            float v0 = 0.0f, v1 = 0.0f;
#pragma unroll
            for (int m = 0; m < 2; ++m) {
                int mt = 2 * p + m;
                v0 = fmaxf(v0, fmaxf(fmaf(acc[mt][nt][0], s0, b0),
                                     fmaf(acc[mt][nt][2], s0, b0)));
                v1 = fmaxf(v1, fmaxf(fmaf(acc[mt][nt][1], s1v, b1v),
                                     fmaf(acc[mt][nt][3], s1v, b1v)));
            }
#pragma unroll
            for (int o = 4; o < 32; o <<= 1) {
                v0 = fmaxf(v0, __shfl_xor_sync(0xffffffffu, v0, o));
                v1 = fmaxf(v1, __shfl_xor_sync(0xffffffffu, v1, o));
            }
            if ((lane >> 2) == 0) {
                int g2 = blockIdx.x * 4 + mh * 2 + p;
                int bb = g2 >> 7, si = g2 & 127;
                out[((size_t)bb * 256 + col) * 128 + si]     = v0;
                out[((size_t)bb * 256 + col + 1) * 128 + si] = v1;
            }
        }
    }
}

// ---------------- launch ----------------
extern "C" void kernel_launch(void* const* d_in, const int* in_sizes, int n_in,
                              void* d_out, int out_size) {
    const float* xyz   = (const float*)d_in[0];
    const float* feats = (const float*)d_in[1];
    const float* w1    = (const float*)d_in[2];
    const float* g1    = (const float*)d_in[3];
    const float* be1   = (const float*)d_in[4];
    const float* m1    = (const float*)d_in[5];
    const float* v1    = (const float*)d_in[6];
    const float* w2    = (const float*)d_in[7];
    const float* g2    = (const float*)d_in[8];
    const float* be2   = (const float*)d_in[9];
    const float* m2    = (const float*)d_in[10];
    const float* v2    = (const float*)d_in[11];
    float* out = (float*)d_out;

    cudaFuncSetAttribute(fused_gemm_kernel, cudaFuncAttributeMaxDynamicSharedMemorySize, GSMEM);

    prep_kernel<<<544, 256>>>(w1, w2, g1, be1, m1, v1, g2, be2, m2, v2);
    fps_kernel<<<BATCH * 8, 1024>>>(xyz);
    bq_gather_kernel<<<BATCH * NPOINT, 256>>>(xyz, feats);
    fused_gemm_kernel<<<NTILE, 512, GSMEM>>>(out);
}

// round 6
// speedup vs baseline: 2.2277x; 1.1155x over previous
#include <cuda_runtime.h>
#include <cuda_fp16.h>
#include <cstdint>

#define BATCH   8
#define NPTS    16384
#define NPOINT  128
#define NSAMPLE 32
#define C_IN    256
#define C1      259
#define K1      288
#define K2      256
#define NTILE   256
#define R2      0.16f
#define BN_EPS  1e-5f

// fused gemm smem layout (A: single fp16 matrix; W: fp16 hi+lo chunks)
#define SAB    592                      // bytes per A row (576 data + 16 pad)
#define A_SZ   (128 * SAB)              // 75776
#define W_OFF  A_SZ
#define WCH    24576                    // one weight chunk: hi 12288 + lo 12288
#define GSMEM  (W_OFF + 3 * WCH)        // 149504
#define NCH    (K1 / 16 + K2 / 16)      // 34 chunks total

// ---------------- device scratch ----------------
__device__ int d_inds[BATCH * NPOINT];
__device__ __align__(16) __half d_xh[(size_t)NTILE * 128 * K1];
__device__ __align__(16) __half d_w1h[256 * K1];
__device__ __align__(16) __half d_w1l[256 * K1];
__device__ __align__(16) __half d_w2h[256 * K2];
__device__ __align__(16) __half d_w2l[256 * K2];
__device__ float d_s1[256], d_b1[256], d_s2[256], d_b2[256];

// ---------------- low-level helpers ----------------
__device__ __forceinline__ uint32_t smem_u32(const void* p) {
    uint32_t a;
    asm("{ .reg .u64 t; cvta.to.shared.u64 t, %1; cvt.u32.u64 %0, t; }" : "=r"(a) : "l"(p));
    return a;
}
__device__ __forceinline__ void cp16(uint32_t dst, const void* src) {
    uint64_t g = __cvta_generic_to_global(src);
    asm volatile("cp.async.cg.shared.global [%0], [%1], 16;" :: "r"(dst), "l"(g) : "memory");
}
__device__ __forceinline__ void cp_commit() {
    asm volatile("cp.async.commit_group;" ::: "memory");
}
template<int N> __device__ __forceinline__ void cp_wait() {
    asm volatile("cp.async.wait_group %0;" :: "n"(N) : "memory");
}
__device__ __forceinline__ void ldsm4(uint32_t& r0, uint32_t& r1, uint32_t& r2, uint32_t& r3, uint32_t addr) {
    asm volatile("ldmatrix.sync.aligned.m8n8.x4.shared.b16 {%0,%1,%2,%3}, [%4];"
                 : "=r"(r0), "=r"(r1), "=r"(r2), "=r"(r3) : "r"(addr));
}
__device__ __forceinline__ void mma16816(float* d, const uint32_t* a, const uint32_t* b) {
    asm volatile(
        "mma.sync.aligned.m16n8k16.row.col.f32.f16.f16.f32 "
        "{%0,%1,%2,%3}, {%4,%5,%6,%7}, {%8,%9}, {%0,%1,%2,%3};"
        : "+f"(d[0]), "+f"(d[1]), "+f"(d[2]), "+f"(d[3])
        : "r"(a[0]), "r"(a[1]), "r"(a[2]), "r"(a[3]), "r"(b[0]), "r"(b[1]));
}
__device__ __forceinline__ uint32_t pack_h2(float v0, float v1) {
    __half h0 = __float2half_rn(v0), h1 = __float2half_rn(v1);
    return (uint32_t)__half_as_ushort(h0) | ((uint32_t)__half_as_ushort(h1) << 16);
}
__device__ __forceinline__ void st_cluster_u64(uint32_t saddr, uint32_t rank, unsigned long long v) {
    asm volatile("{\n\t.reg .b32 r;\n\tmapa.shared::cluster.u32 r, %0, %1;\n\t"
                 "st.shared::cluster.u64 [r], %2;\n\t}"
                 :: "r"(saddr), "r"(rank), "l"(v) : "memory");
}
__device__ __forceinline__ void st_cluster_f32(uint32_t saddr, uint32_t rank, float v) {
    asm volatile("{\n\t.reg .b32 r;\n\tmapa.shared::cluster.u32 r, %0, %1;\n\t"
                 "st.shared::cluster.f32 [r], %2;\n\t}"
                 :: "r"(saddr), "r"(rank), "f"(v) : "memory");
}
__device__ __forceinline__ void cluster_sync_() {
    asm volatile("barrier.cluster.arrive.aligned;" ::: "memory");
    asm volatile("barrier.cluster.wait.aligned;" ::: "memory");
}

// ---------------- FPS: cluster of 8 CTAs per batch, points in registers ----------------
__global__ __cluster_dims__(8, 1, 1) __launch_bounds__(1024, 1)
void fps_kernel(const float* __restrict__ xyz) {
    __shared__ uint32_t redv[32];
    __shared__ int      redi[32];
    __shared__ float    redx[32], redy[32], redz[32];
    __shared__ unsigned long long mb_key[2][8];
    __shared__ float    mb_x[2][8], mb_y[2][8], mb_z[2][8];

    const int b    = blockIdx.x >> 3;
    const int rank = blockIdx.x & 7;
    const int tid  = threadIdx.x;
    const int lane = tid & 31, w = tid >> 5;
    const float* base = xyz + (size_t)b * NPTS * 3;
    const int i0 = rank * 2048 + tid * 2;

    float x0 = base[i0 * 3],     y0 = base[i0 * 3 + 1], z0 = base[i0 * 3 + 2];
    float x1 = base[i0 * 3 + 3], y1 = base[i0 * 3 + 4], z1 = base[i0 * 3 + 5];
    float d0 = 1e10f, d1 = 1e10f;
    float cx = base[0], cy = base[1], cz = base[2];
    int far = 0;

    const uint32_t mbk = smem_u32(&mb_key[0][0]);
    const uint32_t mbx = smem_u32(&mb_x[0][0]);
    const uint32_t mby = smem_u32(&mb_y[0][0]);
    const uint32_t mbz = smem_u32(&mb_z[0][0]);

    cluster_sync_();

    for (int j = 0; j < NPOINT; ++j) {
        if (rank == 0 && tid == 0) d_inds[b * NPOINT + j] = far;
        const int p = j & 1;

        float ax = __fadd_rn(x0, -cx), ay = __fadd_rn(y0, -cy), az = __fadd_rn(z0, -cz);
        float t0 = __fadd_rn(__fadd_rn(__fmul_rn(ax, ax), __fmul_rn(ay, ay)), __fmul_rn(az, az));
        d0 = fminf(d0, t0);
        float bx = __fadd_rn(x1, -cx), by = __fadd_rn(y1, -cy), bz = __fadd_rn(z1, -cz);
        float t1 = __fadd_rn(__fadd_rn(__fmul_rn(bx, bx), __fmul_rn(by, by)), __fmul_rn(bz, bz));
        d1 = fminf(d1, t1);

        float bv; int bi; float wx, wy, wz;
        if (d0 >= d1) { bv = d0; bi = i0;     wx = x0; wy = y0; wz = z0; }
        else          { bv = d1; bi = i0 + 1; wx = x1; wy = y1; wz = z1; }

        uint32_t vb   = __float_as_uint(bv);
        uint32_t vmax = __reduce_max_sync(0xffffffffu, vb);
        uint32_t msk  = __ballot_sync(0xffffffffu, vb == vmax);
        int src = __ffs(msk) - 1;
        if (lane == 0)   redv[w] = vmax;
        if (lane == src) { redi[w] = bi; redx[w] = wx; redy[w] = wy; redz[w] = wz; }
        __syncthreads();

        if (w == 0) {
            uint32_t v2  = redv[lane];
            uint32_t m2  = __reduce_max_sync(0xffffffffu, v2);
            uint32_t mk2 = __ballot_sync(0xffffffffu, v2 == m2);
            int wl = __ffs(mk2) - 1;
            if (lane == 0) {
                int bi2 = redi[wl];
                unsigned long long key =
                    ((unsigned long long)m2 << 32) | (unsigned long long)(0xFFFFFFFFu - (uint32_t)bi2);
                float fx = redx[wl], fy = redy[wl], fz = redz[wl];
                uint32_t so = (uint32_t)(p * 8 + rank);
#pragma unroll
                for (uint32_t t = 0; t < 8; ++t) {
                    st_cluster_u64(mbk + so * 8, t, key);
                    st_cluster_f32(mbx + so * 4, t, fx);
                    st_cluster_f32(mby + so * 4, t, fy);
                    st_cluster_f32(mbz + so * 4, t, fz);
                }
            }
        }
        cluster_sync_();

        unsigned long long bk = mb_key[p][0];
        int bs = 0;
#pragma unroll
        for (int s = 1; s < 8; ++s) {
            unsigned long long k = mb_key[p][s];
            if (k > bk) { bk = k; bs = s; }
        }
        far = (int)(0xFFFFFFFFu - (uint32_t)bk);
        cx = mb_x[p][bs]; cy = mb_y[p][bs]; cz = mb_z[p][bs];
    }
}

// ---------------- ball query + gather (blocks 0..1023) + weight prep (blocks 1024+) ----------------
__global__ __launch_bounds__(256) void bq_prep_kernel(const float* __restrict__ xyz,
                                                      const float* __restrict__ feats,
                                                      const float* __restrict__ w1,
                                                      const float* __restrict__ w2,
                                                      const float* __restrict__ g1, const float* __restrict__ be1,
                                                      const float* __restrict__ m1, const float* __restrict__ v1,
                                                      const float* __restrict__ g2, const float* __restrict__ be2,
                                                      const float* __restrict__ m2, const float* __restrict__ v2) {
    const int tid = threadIdx.x;
    if (blockIdx.x >= 1024) {
        // ---- prep path ----
        if (blockIdx.x == 1024) {
            int o = tid;
            float s = g1[o] / sqrtf(v1[o] + BN_EPS);
            d_s1[o] = s; d_b1[o] = be1[o] - m1[o] * s;
            float t = g2[o] / sqrtf(v2[o] + BN_EPS);
            d_s2[o] = t; d_b2[o] = be2[o] - m2[o] * t;
        }
        int idx = (blockIdx.x - 1024) * 256 + tid;
        const int T1 = 256 * K1;
        float v; __half *ph, *pl; int e;
        if (idx < T1) {
            int o = idx / K1, c = idx - o * K1;
            v = (c < C1) ? w1[o * C1 + c] : 0.0f;
            ph = d_w1h; pl = d_w1l; e = o * K1 + c;
        } else {
            int k = idx - T1;
            if (k >= 256 * K2) return;
            int o = k >> 8, c = k & 255;
            v = w2[o * 256 + c];
            ph = d_w2h; pl = d_w2l; e = o * K2 + c;
        }
        __half hb = __float2half_rn(v);
        ph[e] = hb;
        pl[e] = __float2half_rn(v - __half2float(hb));
        return;
    }

    __shared__ int   sidx[NSAMPLE];
    __shared__ float ctr[3];
    const int g = blockIdx.x;
    const int b = g >> 7;
    const float* xb = xyz + (size_t)b * NPTS * 3;

    if (tid < 32) {
        int ind = d_inds[g];
        float cx = xb[ind * 3], cy = xb[ind * 3 + 1], cz = xb[ind * 3 + 2];
        if (tid == 0) { ctr[0] = cx; ctr[1] = cy; ctr[2] = cz; }
        int cnt = 0;
        for (int basei = 0; basei < NPTS && cnt < NSAMPLE; basei += 32) {
            int i = basei + tid;
            float dx = __fadd_rn(cx, -xb[i * 3]);
            float dy = __fadd_rn(cy, -xb[i * 3 + 1]);
            float dz = __fadd_rn(cz, -xb[i * 3 + 2]);
            float d2 = __fadd_rn(__fadd_rn(__fmul_rn(dx, dx), __fmul_rn(dy, dy)), __fmul_rn(dz, dz));
            bool pred = d2 < R2;
            unsigned m = __ballot_sync(0xffffffffu, pred);
            int r    = __popc(m & ((1u << tid) - 1u));
            int take = min(__popc(m), NSAMPLE - cnt);
            if (pred && r < take) sidx[cnt + r] = i;
            cnt += take;
        }
        __syncwarp();
        if (cnt < NSAMPLE) {
            int f = sidx[0];
            for (int pos = cnt + tid; pos < NSAMPLE; pos += 32) sidx[pos] = f;
        }
    }
    __syncthreads();

    const float* fb = feats + (size_t)b * NPTS * C_IN;
    const size_t tbase = ((size_t)(g >> 2) * 128 + (size_t)(g & 3) * 32) * K1;
    for (int idx = tid; idx < 32 * (K1 / 2); idx += 256) {
        int k = idx / (K1 / 2), q = idx - k * (K1 / 2);
        int c0 = 2 * q, c1 = c0 + 1;
        int p = sidx[k];
        float v0 = (c0 < 3) ? __fadd_rn(xb[p * 3 + c0], -ctr[c0])
                 : (c0 < C1 ? fb[(size_t)p * C_IN + (c0 - 3)] : 0.0f);
        float v1 = (c1 < 3) ? __fadd_rn(xb[p * 3 + c1], -ctr[c1])
                 : (c1 < C1 ? fb[(size_t)p * C_IN + (c1 - 3)] : 0.0f);
        *(uint32_t*)((char*)d_xh + (tbase + (size_t)k * K1 + c0) * 2) = pack_h2(v0, v1);
    }
}

// ---------------- fused GEMM1 + GEMM2 + maxpool (fp16 2-pass, 1 sync/chunk) ----------------
__global__ __launch_bounds__(512, 1) void fused_gemm_kernel(float* __restrict__ out) {
    extern __shared__ __align__(128) char smem[];
    const uint32_t sb = smem_u32(smem);
    const int tid  = threadIdx.x;
    const int lane = tid & 31, wid = tid >> 5;
    const int mh = wid >> 3, nb = wid & 7;

    auto load_chunk = [&](int ci) {
        const __half *sh, *sl; int koff, kstr;
        if (ci < 18) { sh = d_w1h; sl = d_w1l; koff = ci * 16;        kstr = K1; }
        else         { sh = d_w2h; sl = d_w2l; koff = (ci - 18) * 16; kstr = K2; }
        uint32_t dstb = sb + W_OFF + (ci % 3) * WCH;
        for (int i = tid; i < 1024; i += 512) {
            int mat = i >> 9, rem = i & 511, o = rem >> 1, s2 = rem & 1;
            cp16(dstb + mat * 12288 + o * 48 + s2 * 16,
                 (mat ? sl : sh) + o * kstr + koff + s2 * 8);
        }
    };

    // prologue: A tile + chunk 0 -> group0 ; chunk 1 -> group1
    {
        const size_t gbase = (size_t)blockIdx.x * 128 * K1;
        constexpr int asegs = K1 / 8;          // 36
#pragma unroll
        for (int i = tid; i < 128 * asegs; i += 512) {
            int r = i / asegs, s = i - r * asegs;
            cp16(sb + r * SAB + s * 16, d_xh + gbase + (size_t)r * K1 + s * 8);
        }
        load_chunk(0); cp_commit();
        load_chunk(1); cp_commit();
    }

    float acc[4][4][4];
#pragma unroll
    for (int a = 0; a < 4; ++a)
#pragma unroll
        for (int b2 = 0; b2 < 4; ++b2)
#pragma unroll
            for (int c = 0; c < 4; ++c) acc[a][b2][c] = 0.0f;

    const int lr   = lane & 15;
    const int ahi  = (lane >> 4) * 16;
    const int brow = (lane & 7) | ((lane >> 4) << 3);
    const int bko  = ((lane >> 3) & 1) * 16;

    for (int g = 0; g < NCH; ++g) {
        cp_wait<1>();
        __syncthreads();   // chunk g arrived; all warps done with iter g-1 (buf (g-1)%3 reusable)

        if (g == 18) {
            // ---- epilogue 1: BN1+ReLU -> fp16 h overwrites A region ----
#pragma unroll
            for (int mt = 0; mt < 4; ++mt) {
                int row0 = mh * 64 + mt * 16 + (lane >> 2);
#pragma unroll
                for (int nt = 0; nt < 4; ++nt) {
                    int col = nb * 32 + nt * 8 + 2 * (lane & 3);
                    float s0 = d_s1[col], s1v = d_s1[col + 1];
                    float b0 = d_b1[col], b1v = d_b1[col + 1];
                    float f00 = fmaxf(fmaf(acc[mt][nt][0], s0, b0), 0.0f);
                    float f01 = fmaxf(fmaf(acc[mt][nt][1], s1v, b1v), 0.0f);
                    float f10 = fmaxf(fmaf(acc[mt][nt][2], s0, b0), 0.0f);
                    float f11 = fmaxf(fmaf(acc[mt][nt][3], s1v, b1v), 0.0f);
                    uint32_t o0 = (uint32_t)row0 * SAB + (uint32_t)col * 2;
                    *(uint32_t*)(smem + o0)           = pack_h2(f00, f01);
                    *(uint32_t*)(smem + o0 + 8 * SAB) = pack_h2(f10, f11);
                    acc[mt][nt][0] = 0.0f; acc[mt][nt][1] = 0.0f;
                    acc[mt][nt][2] = 0.0f; acc[mt][nt][3] = 0.0f;
                }
            }
            __syncthreads();   // h visible to all warps before iter-18 ldsm reads
        }

        // prefetch chunk g+2 into buf (g+2)%3 == (g-1)%3 (safe: everyone passed the sync)
        if (g + 2 < NCH) load_chunk(g + 2);
        cp_commit();

        const int buf = g % 3;
        const uint32_t bbase = sb + W_OFF + buf * WCH + (nb * 32 + brow) * 48 + bko;
        uint32_t bh[4][2], bl[4][2];
#pragma unroll
        for (int ntp = 0; ntp < 2; ++ntp) {
            uint32_t r0, r1, r2, r3;
            ldsm4(r0, r1, r2, r3, bbase + ntp * 16 * 48);
            bh[ntp * 2][0] = r0; bh[ntp * 2][1] = r1;
            bh[ntp * 2 + 1][0] = r2; bh[ntp * 2 + 1][1] = r3;
            ldsm4(r0, r1, r2, r3, bbase + ntp * 16 * 48 + 12288);
            bl[ntp * 2][0] = r0; bl[ntp * 2][1] = r1;
            bl[ntp * 2 + 1][0] = r2; bl[ntp * 2 + 1][1] = r3;
        }

        const int kb = (g < 18 ? g : g - 18) * 32;
#pragma unroll
        for (int mt = 0; mt < 4; ++mt) {
            const uint32_t arow = sb + (mh * 64 + mt * 16 + lr) * SAB + kb + ahi;
            uint32_t a[4];
            ldsm4(a[0], a[1], a[2], a[3], arow);
#pragma unroll
            for (int nt = 0; nt < 4; ++nt) mma16816(acc[mt][nt], a, bh[nt]);
#pragma unroll
            for (int nt = 0; nt < 4; ++nt) mma16816(acc[mt][nt], a, bl[nt]);
        }
    }

    // ---- epilogue 2: BN2+ReLU + maxpool(32) -> out[b][o][s] ----
#pragma unroll
    for (int p = 0; p < 2; ++p) {
#pragma unroll
        for (int nt = 0; nt < 4; ++nt) {
            int col = nb * 32 + nt * 8 + 2 * (lane & 3);
            float s0 = d_s2[col], s1v = d_s2[col + 1];
            float b0 = d_b2[col], b1v = d_b2[col + 1];
            float v0 = 0.0f, v1 = 0.0f;
#pragma unroll
            for (int m = 0; m < 2; ++m) {
                int mt = 2 * p + m;
                v0 = fmaxf(v0, fmaxf(fmaf(acc[mt][nt][0], s0, b0),
                                     fmaf(acc[mt][nt][2], s0, b0)));
                v1 = fmaxf(v1, fmaxf(fmaf(acc[mt][nt][1], s1v, b1v),
                                     fmaf(acc[mt][nt][3], s1v, b1v)));
            }
#pragma unroll
            for (int o = 4; o < 32; o <<= 1) {
                v0 = fmaxf(v0, __shfl_xor_sync(0xffffffffu, v0, o));
                v1 = fmaxf(v1, __shfl_xor_sync(0xffffffffu, v1, o));
            }
            if ((lane >> 2) == 0) {
                int g2 = blockIdx.x * 4 + mh * 2 + p;
                int bb = g2 >> 7, si = g2 & 127;
                out[((size_t)bb * 256 + col) * 128 + si]     = v0;
                out[((size_t)bb * 256 + col + 1) * 128 + si] = v1;
            }
        }
    }
}

// ---------------- launch ----------------
extern "C" void kernel_launch(void* const* d_in, const int* in_sizes, int n_in,
                              void* d_out, int out_size) {
    const float* xyz   = (const float*)d_in[0];
    const float* feats = (const float*)d_in[1];
    const float* w1    = (const float*)d_in[2];
    const float* g1    = (const float*)d_in[3];
    const float* be1   = (const float*)d_in[4];
    const float* m1    = (const float*)d_in[5];
    const float* v1    = (const float*)d_in[6];
    const float* w2    = (const float*)d_in[7];
    const float* g2    = (const float*)d_in[8];
    const float* be2   = (const float*)d_in[9];
    const float* m2    = (const float*)d_in[10];
    const float* v2    = (const float*)d_in[11];
    float* out = (float*)d_out;

    cudaFuncSetAttribute(fused_gemm_kernel, cudaFuncAttributeMaxDynamicSharedMemorySize, GSMEM);

    fps_kernel<<<BATCH * 8, 1024>>>(xyz);
    bq_prep_kernel<<<1024 + 544, 256>>>(xyz, feats, w1, w2,
                                        g1, be1, m1, v1, g2, be2, m2, v2);
    fused_gemm_kernel<<<NTILE, 512, GSMEM>>>(out);
}